// round 15
// baseline (speedup 1.0000x reference)
#include <cuda_runtime.h>
#include <cuda_bf16.h>
#include <cstdint>

#define MTOT 8192
#define SEQ  2048
#define HEADS 16
#define NDIM 1024

__device__ float g_q[MTOT * NDIM];
__device__ float g_k[MTOT * NDIM];
__device__ float g_v[MTOT * NDIM];
__device__ float g_att[MTOT * NDIM];

// ---- helpers ----
__device__ __forceinline__ uint32_t cvt_tf32(float x) {
    uint32_t u; asm("cvt.rna.tf32.f32 %0, %1;" : "=r"(u) : "f"(x));
    return u;
}
__device__ __forceinline__ void split2(float x, float y, uint32_t& hi, uint32_t& lo) {
    __nv_bfloat162 h = __floats2bfloat162_rn(x, y);
    float hx = __bfloat162float(h.x), hy = __bfloat162float(h.y);
    __nv_bfloat162 l = __floats2bfloat162_rn(x - hx, y - hy);
    hi = *(uint32_t*)&h;
    lo = *(uint32_t*)&l;
}
__device__ __forceinline__ void mma_tf32(float* c, const uint32_t* a, uint32_t b0, uint32_t b1) {
    asm volatile(
        "mma.sync.aligned.m16n8k8.row.col.f32.tf32.tf32.f32 "
        "{%0,%1,%2,%3}, {%4,%5,%6,%7}, {%8,%9}, {%0,%1,%2,%3};"
        : "+f"(c[0]), "+f"(c[1]), "+f"(c[2]), "+f"(c[3])
        : "r"(a[0]), "r"(a[1]), "r"(a[2]), "r"(a[3]), "r"(b0), "r"(b1));
}
__device__ __forceinline__ void mma_bf16(float* c, const uint32_t* a, uint32_t b0, uint32_t b1) {
    asm volatile(
        "mma.sync.aligned.m16n8k16.row.col.f32.bf16.bf16.f32 "
        "{%0,%1,%2,%3}, {%4,%5,%6,%7}, {%8,%9}, {%0,%1,%2,%3};"
        : "+f"(c[0]), "+f"(c[1]), "+f"(c[2]), "+f"(c[3])
        : "r"(a[0]), "r"(a[1]), "r"(a[2]), "r"(a[3]), "r"(b0), "r"(b1));
}
__device__ __forceinline__ uint32_t smem_u32p(const void* p) {
    return (uint32_t)__cvta_generic_to_shared(p);
}
__device__ __forceinline__ void cp16(uint32_t dst, const void* src) {
    asm volatile("cp.async.cg.shared.global [%0], [%1], 16;" :: "r"(dst), "l"(src));
}
#define CP_COMMIT() asm volatile("cp.async.commit_group;" ::: "memory")
#define CP_WAIT1()  asm volatile("cp.async.wait_group 1;" ::: "memory")
#define CP_WAIT0()  asm volatile("cp.async.wait_group 0;" ::: "memory")

// =================== GEMM (tf32, 128x64 tile, 128 thr, 4 CTAs/SM) ===================
// 4 warps (2m x 2n), warp tile 64x32 (per-warp math identical to R14), K-chunk 16,
// 3-stage cp.async ring. Stage: A [128][20] u32 (2560) + B [16][72] u32 (1152)
// = 3712 u32 = 14848 B. 3 stages = 44544 B -> 4 CTAs/SM (regs capped at 128).
#define NSTG 3
#define STG_U32 3712
#define SB_OFF 2560
#define GEMM_SMEM (NSTG * STG_U32 * 4)

__device__ __forceinline__ void gemm_body(const float* __restrict__ A,
                                          const float* __restrict__ W,
                                          float* __restrict__ C) {
    extern __shared__ uint32_t smw[];
    const uint32_t sbase = smem_u32p(smw);

    const int tid = threadIdx.x, w = tid >> 5, l = tid & 31;
    const int lq = l >> 2, lr = l & 3;
    const int m0 = (w >> 1) * 64, n0 = (w & 1) * 32;
    const int bm = blockIdx.y * 128, bn = blockIdx.x * 64;

    // loaders: A — row = tid (0..127), 16 floats (4 cp16); B — kr = tid>>3, nc = (tid&7)*8
    const int kr = tid >> 3, nc = (tid & 7) * 8;

    const float* arow = A + (size_t)(bm + tid) * 1024;
    const float* brow = W + (size_t)kr * 1024 + bn + nc;
    const uint32_t dA0 = sbase + (uint32_t)(tid * 20) * 4;
    const uint32_t dB0 = sbase + (uint32_t)(SB_OFF + kr * 72 + nc) * 4;

#define G_ISSUE(p, c) do {                                                    \
        uint32_t dA = dA0 + (uint32_t)(p) * (STG_U32 * 4);                    \
        const float* ap = arow + (c) * 16;                                    \
        cp16(dA, ap); cp16(dA + 16, ap + 4);                                  \
        cp16(dA + 32, ap + 8); cp16(dA + 48, ap + 12);                        \
        uint32_t dB = dB0 + (uint32_t)(p) * (STG_U32 * 4);                    \
        const float* bp = brow + (size_t)(c) * 16 * 1024;                     \
        cp16(dB, bp); cp16(dB + 16, bp + 4);                                  \
    } while (0)

    float acc[4][4][4];
#pragma unroll
    for (int i = 0; i < 4; i++)
#pragma unroll
        for (int j = 0; j < 4; j++)
#pragma unroll
            for (int e = 0; e < 4; e++) acc[i][j][e] = 0.0f;

    G_ISSUE(0, 0); CP_COMMIT();
    G_ISSUE(1, 1); CP_COMMIT();

    int st = 0, ist = 2;
    for (int c = 0; c < 64; c++) {
        CP_WAIT1();
        __syncthreads();   // chunk c resident; stage ist free

        if (c + 2 < 64) G_ISSUE(ist, c + 2);
        CP_COMMIT();

        const float* sA = (const float*)smw + st * STG_U32;
        const float* sB = sA + SB_OFF;
#pragma unroll
        for (int s = 0; s < 2; s++) {
            uint32_t a[4][4];
#pragma unroll
            for (int mf = 0; mf < 4; mf++) {
                const float* p = &sA[(m0 + mf * 16 + lq) * 20 + s * 8 + lr];
                a[mf][0] = cvt_tf32(p[0]);
                a[mf][1] = cvt_tf32(p[8 * 20]);
                a[mf][2] = cvt_tf32(p[4]);
                a[mf][3] = cvt_tf32(p[8 * 20 + 4]);
            }
            const float* q0p = &sB[(s * 8 + lr) * 72 + n0 + lq];
            const float* q1p = q0p + 4 * 72;
#pragma unroll
            for (int jf = 0; jf < 4; jf++) {
                uint32_t b0 = cvt_tf32(q0p[jf * 8]);
                uint32_t b1 = cvt_tf32(q1p[jf * 8]);
                mma_tf32(acc[0][jf], a[0], b0, b1);
                mma_tf32(acc[1][jf], a[1], b0, b1);
                mma_tf32(acc[2][jf], a[2], b0, b1);
                mma_tf32(acc[3][jf], a[3], b0, b1);
            }
        }
        st = (st == NSTG - 1) ? 0 : st + 1;
        ist = (ist == NSTG - 1) ? 0 : ist + 1;
    }

#pragma unroll
    for (int mf = 0; mf < 4; mf++)
#pragma unroll
        for (int jf = 0; jf < 4; jf++) {
            int row = bm + m0 + mf * 16 + lq;
            int col = bn + n0 + jf * 8 + lr * 2;
            *(float2*)(C + (size_t)row * 1024 + col) =
                make_float2(acc[mf][jf][0], acc[mf][jf][1]);
            *(float2*)(C + (size_t)(row + 8) * 1024 + col) =
                make_float2(acc[mf][jf][2], acc[mf][jf][3]);
        }
#undef G_ISSUE
}

__global__ void __launch_bounds__(128, 4)
qkv_mma(const float* __restrict__ A, const float* __restrict__ Wq,
        const float* __restrict__ Wk, const float* __restrict__ Wv) {
    const float* W = (blockIdx.z == 0) ? Wq : (blockIdx.z == 1) ? Wk : Wv;
    float* C       = (blockIdx.z == 0) ? g_q : (blockIdx.z == 1) ? g_k : g_v;
    gemm_body(A, W, C);
}
__global__ void __launch_bounds__(128, 4)
out_mma(const float* __restrict__ Wo, float* __restrict__ out) {
    gemm_body(g_att, Wo, out);
}

// =================== Attention (exact R14/R10 version — best known) ===================
#define AKSTG 34816
#define ATT_SMEM (2 * AKSTG + 2 * 17408)

__global__ void attn_mma() {
    extern __shared__ char sm[];
    float* smKf = (float*)sm;
    char* smVh = sm + 2 * AKSTG;
    char* smVl = sm + 2 * AKSTG + 17408;
    float* smM = (float*)sm;

    const int tid = threadIdx.x, w = tid >> 5, l = tid & 31;
    const int lq = l >> 2, lr = l & 3;
    const int qg = w >> 1, kh = w & 1;
    const int b = blockIdx.y >> 4, h = blockIdx.y & 15;
    const size_t base = (size_t)b * SEQ * NDIM + (size_t)h * 64;
    const int q0 = blockIdx.x * 128;
    const int rowbase = q0 + qg * 32;
    const uint32_t skbase = smem_u32p(smKf);

#define AK_ISSUE(stg, j0) do {                                                \
        uint32_t dst0 = skbase + (uint32_t)(stg) * AKSTG;                     \
        _Pragma("unroll")                                                     \
        for (int r = 0; r < 8; r++) {                                         \
            int f = tid + r * 256;                                            \
            int key = f >> 4, seg = (f & 15) * 4;                             \
            cp16(dst0 + (uint32_t)(key * 272 + seg * 4),                      \
                 g_k + base + (size_t)((j0) + key) * 1024 + seg);             \
        }                                                                     \
    } while (0)

    uint32_t qf[8][2][4];
#pragma unroll
    for (int s = 0; s < 8; s++)
#pragma unroll
        for (int mf = 0; mf < 2; mf++) {
            const float* qp = g_q + base + (size_t)(rowbase + mf * 16 + lq) * 1024;
            int col = s * 8 + lr;
            qf[s][mf][0] = cvt_tf32(qp[col] * 0.125f);
            qf[s][mf][1] = cvt_tf32(qp[8 * 1024 + col] * 0.125f);
            qf[s][mf][2] = cvt_tf32(qp[col + 4] * 0.125f);
            qf[s][mf][3] = cvt_tf32(qp[8 * 1024 + col + 4] * 0.125f);
        }

    AK_ISSUE(0, 0); CP_COMMIT();

    float o[2][8][4];
#pragma unroll
    for (int i = 0; i < 2; i++)
#pragma unroll
        for (int j = 0; j < 8; j++)
#pragma unroll
            for (int e = 0; e < 4; e++) o[i][j][e] = 0.0f;
    float rsa[2][2] = {{0.0f, 0.0f}, {0.0f, 0.0f}};

    for (int t = 0; t < 16; t++) {
        const int j0 = t * 128;
        const int st = t & 1;

        float4 vv[8];
#pragma unroll
        for (int r = 0; r < 8; r++) {
            int f = tid + r * 256;
            vv[r] = *(const float4*)(g_v + base + (size_t)(j0 + (f >> 4)) * 1024 + (f & 15) * 4);
        }

        CP_WAIT0();
        __syncthreads();

        if (t < 15) AK_ISSUE(st ^ 1, j0 + 128);
        CP_COMMIT();

        const float* sK = smKf + st * (AKSTG / 4);
        float sc[2][8][4];
#pragma unroll
        for (int i = 0; i < 2; i++)
#pragma unroll
            for (int j = 0; j < 8; j++)
#pragma unroll
                for (int e = 0; e < 4; e++) sc[i][j][e] = 0.0f;
#pragma unroll
        for (int s = 0; s < 8; s++) {
#pragma unroll
            for (int jf = 0; jf < 8; jf++) {
                const float* p = &sK[(kh * 64 + jf * 8 + lq) * 68 + s * 8 + lr];
                uint32_t b0 = cvt_tf32(p[0]);
                uint32_t b1 = cvt_tf32(p[4]);
                mma_tf32(sc[0][jf], qf[s][0], b0, b1);
                mma_tf32(sc[1][jf], qf[s][1], b0, b1);
            }
        }

#pragma unroll
        for (int mf = 0; mf < 2; mf++)
#pragma unroll
            for (int jf = 0; jf < 8; jf++) {
                float e0 = __expf(sc[mf][jf][0]);
                float e1 = __expf(sc[mf][jf][1]);
                float e2 = __expf(sc[mf][jf][2]);
                float e3 = __expf(sc[mf][jf][3]);
                sc[mf][jf][0] = e0; sc[mf][jf][1] = e1;
                sc[mf][jf][2] = e2; sc[mf][jf][3] = e3;
                rsa[mf][0] += e0 + e1;
                rsa[mf][1] += e2 + e3;
            }

#pragma unroll
        for (int r = 0; r < 8; r++) {
            int f = tid + r * 256;
            int key = f >> 4, d4 = (f & 15) * 4;
            float x[4] = {vv[r].x, vv[r].y, vv[r].z, vv[r].w};
#pragma unroll
            for (int i = 0; i < 4; i++) {
                __nv_bfloat16 hb = __float2bfloat16(x[i]);
                __nv_bfloat16 lb = __float2bfloat16(x[i] - __bfloat162float(hb));
                *(__nv_bfloat16*)(smVh + (d4 + i) * 272 + key * 2) = hb;
                *(__nv_bfloat16*)(smVl + (d4 + i) * 272 + key * 2) = lb;
            }
        }
        __syncthreads();

#pragma unroll
        for (int kk = 0; kk < 4; kk++) {
            uint32_t ph[2][4], pl[2][4];
#pragma unroll
            for (int mf = 0; mf < 2; mf++) {
                split2(sc[mf][2 * kk][0],     sc[mf][2 * kk][1],     ph[mf][0], pl[mf][0]);
                split2(sc[mf][2 * kk][2],     sc[mf][2 * kk][3],     ph[mf][1], pl[mf][1]);
                split2(sc[mf][2 * kk + 1][0], sc[mf][2 * kk + 1][1], ph[mf][2], pl[mf][2]);
                split2(sc[mf][2 * kk + 1][2], sc[mf][2 * kk + 1][3], ph[mf][3], pl[mf][3]);
            }
            const int keyb = (kh * 64 + kk * 16 + lr * 2) * 2;
#pragma unroll
            for (int jf = 0; jf < 8; jf++) {
                const char* pv = smVh + (jf * 8 + lq) * 272 + keyb;
                uint32_t w0 = *(const uint32_t*)pv;
                uint32_t w2 = *(const uint32_t*)(pv + 16);
                const char* pw = smVl + (jf * 8 + lq) * 272 + keyb;
                uint32_t v0 = *(const uint32_t*)pw;
                uint32_t v2 = *(const uint32_t*)(pw + 16);
                mma_bf16(o[0][jf], ph[0], w0, w2);
                mma_bf16(o[0][jf], pl[0], w0, w2);
                mma_bf16(o[0][jf], ph[0], v0, v2);
                mma_bf16(o[1][jf], ph[1], w0, w2);
                mma_bf16(o[1][jf], pl[1], w0, w2);
                mma_bf16(o[1][jf], ph[1], v0, v2);
            }
        }
    }

#pragma unroll
    for (int i = 0; i < 2; i++)
#pragma unroll
        for (int hh = 0; hh < 2; hh++) {
            rsa[i][hh] += __shfl_xor_sync(0xffffffffu, rsa[i][hh], 1);
            rsa[i][hh] += __shfl_xor_sync(0xffffffffu, rsa[i][hh], 2);
        }
    __syncthreads();
    if (kh == 1) {
#pragma unroll
        for (int mf = 0; mf < 2; mf++)
#pragma unroll
            for (int jf = 0; jf < 8; jf++)
#pragma unroll
                for (int e = 0; e < 4; e++) {
                    int idx = (mf * 8 + jf) * 4 + e;
                    smM[idx * 128 + qg * 32 + l] = o[mf][jf][e];
                }
#pragma unroll
        for (int i = 0; i < 4; i++)
            smM[8192 + i * 128 + qg * 32 + l] = rsa[i >> 1][i & 1];
    }
    __syncthreads();
    if (kh == 0) {
        float inv[2][2];
#pragma unroll
        for (int i = 0; i < 4; i++) {
            float tot = rsa[i >> 1][i & 1] + smM[8192 + i * 128 + qg * 32 + l];
            inv[i >> 1][i & 1] = 1.0f / tot;
        }
#pragma unroll
        for (int mf = 0; mf < 2; mf++)
#pragma unroll
            for (int jf = 0; jf < 8; jf++) {
                int idx = (mf * 8 + jf) * 4;
                float r0 = o[mf][jf][0] + smM[(idx + 0) * 128 + qg * 32 + l];
                float r1 = o[mf][jf][1] + smM[(idx + 1) * 128 + qg * 32 + l];
                float r2 = o[mf][jf][2] + smM[(idx + 2) * 128 + qg * 32 + l];
                float r3 = o[mf][jf][3] + smM[(idx + 3) * 128 + qg * 32 + l];
                int row = rowbase + mf * 16 + lq;
                int col = jf * 8 + lr * 2;
                *(float2*)(g_att + base + (size_t)row * 1024 + col) =
                    make_float2(r0 * inv[mf][0], r1 * inv[mf][0]);
                *(float2*)(g_att + base + (size_t)(row + 8) * 1024 + col) =
                    make_float2(r2 * inv[mf][1], r3 * inv[mf][1]);
            }
    }
#undef AK_ISSUE
}

// =================== launch ===================
extern "C" void kernel_launch(void* const* d_in, const int* in_sizes, int n_in,
                              void* d_out, int out_size) {
    const float* hidden = (const float*)d_in[0];
    const float* wq     = (const float*)d_in[1];
    const float* wk     = (const float*)d_in[2];
    const float* wv     = (const float*)d_in[3];
    const float* wo     = (const float*)d_in[4];
    float* out = (float*)d_out;

    cudaFuncSetAttribute(qkv_mma, cudaFuncAttributeMaxDynamicSharedMemorySize, GEMM_SMEM);
    cudaFuncSetAttribute(out_mma, cudaFuncAttributeMaxDynamicSharedMemorySize, GEMM_SMEM);
    cudaFuncSetAttribute(attn_mma, cudaFuncAttributeMaxDynamicSharedMemorySize, ATT_SMEM);

    dim3 qkv_grid(16, 64, 3);
    qkv_mma<<<qkv_grid, 128, GEMM_SMEM>>>(hidden, wq, wk, wv);

    dim3 fa_grid(SEQ / 128, (MTOT / SEQ) * HEADS);  // (16, 64)
    attn_mma<<<fa_grid, 256, ATT_SMEM>>>();

    dim3 out_grid(16, 64);
    out_mma<<<out_grid, 128, GEMM_SMEM>>>(wo, out);

    (void)in_sizes; (void)n_in; (void)out_size;
}

// round 16
// speedup vs baseline: 1.3333x; 1.3333x over previous
#include <cuda_runtime.h>
#include <cuda_bf16.h>
#include <cstdint>

#define MTOT 8192
#define SEQ  2048
#define HEADS 16
#define NDIM 1024

__device__ float g_q[MTOT * NDIM];
__device__ float g_k[MTOT * NDIM];
__device__ float g_v[MTOT * NDIM];
__device__ float g_att[MTOT * NDIM];

// ---- helpers ----
__device__ __forceinline__ uint32_t cvt_tf32(float x) {
    uint32_t u; asm("cvt.rna.tf32.f32 %0, %1;" : "=r"(u) : "f"(x));
    return u;
}
__device__ __forceinline__ void mma_tf32(float* c, const uint32_t* a, uint32_t b0, uint32_t b1) {
    asm volatile(
        "mma.sync.aligned.m16n8k8.row.col.f32.tf32.tf32.f32 "
        "{%0,%1,%2,%3}, {%4,%5,%6,%7}, {%8,%9}, {%0,%1,%2,%3};"
        : "+f"(c[0]), "+f"(c[1]), "+f"(c[2]), "+f"(c[3])
        : "r"(a[0]), "r"(a[1]), "r"(a[2]), "r"(a[3]), "r"(b0), "r"(b1));
}
__device__ __forceinline__ uint32_t smem_u32p(const void* p) {
    return (uint32_t)__cvta_generic_to_shared(p);
}
__device__ __forceinline__ void cp16(uint32_t dst, const void* src) {
    asm volatile("cp.async.cg.shared.global [%0], [%1], 16;" :: "r"(dst), "l"(src));
}
#define CP_COMMIT() asm volatile("cp.async.commit_group;" ::: "memory")
#define CP_WAIT3()  asm volatile("cp.async.wait_group 3;" ::: "memory")
#define CP_WAIT0()  asm volatile("cp.async.wait_group 0;" ::: "memory")

// =================== GEMM (exact R14: tf32, 128x128 tile, 256 thr, 2 CTAs/SM) ===================
#define NSTG 5
#define STG_U32 4736
#define SB_OFF 2560
#define GEMM_SMEM (NSTG * STG_U32 * 4)

__device__ __forceinline__ void gemm_body(const float* __restrict__ A,
                                          const float* __restrict__ W,
                                          float* __restrict__ C) {
    extern __shared__ uint32_t smw[];
    const uint32_t sbase = smem_u32p(smw);

    const int tid = threadIdx.x, w = tid >> 5, l = tid & 31;
    const int lq = l >> 2, lr = l & 3;
    const int m0 = (w >> 2) * 64, n0 = (w & 3) * 32;
    const int bm = blockIdx.y * 128, bn = blockIdx.x * 128;

    const int arow_i = tid >> 1, ahalf = (tid & 1) * 8;
    const int kr = tid >> 4, nc = (tid & 15) * 8;

    const float* arow = A + (size_t)(bm + arow_i) * 1024 + ahalf;
    const float* brow = W + (size_t)kr * 1024 + bn + nc;
    const uint32_t dA0 = sbase + (uint32_t)(arow_i * 20 + ahalf) * 4;
    const uint32_t dB0 = sbase + (uint32_t)(SB_OFF + kr * 136 + nc) * 4;

#define G_ISSUE(p, c) do {                                                    \
        uint32_t dA = dA0 + (uint32_t)(p) * (STG_U32 * 4);                    \
        const float* ap = arow + (c) * 16;                                    \
        cp16(dA, ap); cp16(dA + 16, ap + 4);                                  \
        uint32_t dB = dB0 + (uint32_t)(p) * (STG_U32 * 4);                    \
        const float* bp = brow + (size_t)(c) * 16 * 1024;                     \
        cp16(dB, bp); cp16(dB + 16, bp + 4);                                  \
    } while (0)

    float acc[4][4][4];
#pragma unroll
    for (int i = 0; i < 4; i++)
#pragma unroll
        for (int j = 0; j < 4; j++)
#pragma unroll
            for (int e = 0; e < 4; e++) acc[i][j][e] = 0.0f;

    G_ISSUE(0, 0); CP_COMMIT();
    G_ISSUE(1, 1); CP_COMMIT();
    G_ISSUE(2, 2); CP_COMMIT();
    G_ISSUE(3, 3); CP_COMMIT();

    int st = 0, ist = 4;
    for (int c = 0; c < 64; c++) {
        CP_WAIT3();
        __syncthreads();

        if (c + 4 < 64) G_ISSUE(ist, c + 4);
        CP_COMMIT();

        const float* sA = (const float*)smw + st * STG_U32;
        const float* sB = sA + SB_OFF;
#pragma unroll
        for (int s = 0; s < 2; s++) {
            uint32_t a[4][4];
#pragma unroll
            for (int mf = 0; mf < 4; mf++) {
                const float* p = &sA[(m0 + mf * 16 + lq) * 20 + s * 8 + lr];
                a[mf][0] = cvt_tf32(p[0]);
                a[mf][1] = cvt_tf32(p[8 * 20]);
                a[mf][2] = cvt_tf32(p[4]);
                a[mf][3] = cvt_tf32(p[8 * 20 + 4]);
            }
            const float* q0p = &sB[(s * 8 + lr) * 136 + n0 + lq];
            const float* q1p = q0p + 4 * 136;
#pragma unroll
            for (int jf = 0; jf < 4; jf++) {
                uint32_t b0 = cvt_tf32(q0p[jf * 8]);
                uint32_t b1 = cvt_tf32(q1p[jf * 8]);
                mma_tf32(acc[0][jf], a[0], b0, b1);
                mma_tf32(acc[1][jf], a[1], b0, b1);
                mma_tf32(acc[2][jf], a[2], b0, b1);
                mma_tf32(acc[3][jf], a[3], b0, b1);
            }
        }
        st = (st == NSTG - 1) ? 0 : st + 1;
        ist = (ist == NSTG - 1) ? 0 : ist + 1;
    }

#pragma unroll
    for (int mf = 0; mf < 4; mf++)
#pragma unroll
        for (int jf = 0; jf < 4; jf++) {
            int row = bm + m0 + mf * 16 + lq;
            int col = bn + n0 + jf * 8 + lr * 2;
            *(float2*)(C + (size_t)row * 1024 + col) =
                make_float2(acc[mf][jf][0], acc[mf][jf][1]);
            *(float2*)(C + (size_t)(row + 8) * 1024 + col) =
                make_float2(acc[mf][jf][2], acc[mf][jf][3]);
        }
#undef G_ISSUE
}

__global__ void __launch_bounds__(256, 2)
qkv_mma(const float* __restrict__ A, const float* __restrict__ Wq,
        const float* __restrict__ Wk, const float* __restrict__ Wv) {
    const float* W = (blockIdx.z == 0) ? Wq : (blockIdx.z == 1) ? Wk : Wv;
    float* C       = (blockIdx.z == 0) ? g_q : (blockIdx.z == 1) ? g_k : g_v;
    gemm_body(A, W, C);
}
__global__ void __launch_bounds__(256, 2)
out_mma(const float* __restrict__ Wo, float* __restrict__ out) {
    gemm_body(g_att, Wo, out);
}

// =================== Attention (tf32 PV via per-warp smem P) ===================
// CTA = (b,h) x 128 q-rows, 8 warps (32q x 64key). 16 KV tiles of 128 keys.
// K: cp.async 2-stage [128][68] f32.  V: cp.async 2-stage [128][72] f32 (natural
// [key][dim] = PV B-operand, conflict-free b-frags).  P: per-warp smem [32][68]
// f32 — STS c-frags post-exp, __syncwarp, LDS as tf32 A-frags (conflict-free).
// One __syncthreads per tile.
#define AKSTG 34816                   // 128*68*4
#define AVSTG 36864                   // 128*72*4
#define APOFF (2 * AKSTG + 2 * AVSTG) // 143360
#define ATT_SMEM (APOFF + 8 * 8704)   // + 8 warps * 32*68*4 = 212992

__global__ void attn_mma() {
    extern __shared__ char sm[];
    float* smKf = (float*)sm;
    float* smVf = (float*)(sm + 2 * AKSTG);
    float* smM = (float*)sm;   // merge scratch (reuses K region)

    const int tid = threadIdx.x, w = tid >> 5, l = tid & 31;
    const int lq = l >> 2, lr = l & 3;
    const int qg = w >> 1, kh = w & 1;
    const int b = blockIdx.y >> 4, h = blockIdx.y & 15;
    const size_t base = (size_t)b * SEQ * NDIM + (size_t)h * 64;
    const int q0 = blockIdx.x * 128;
    const int rowbase = q0 + qg * 32;
    const uint32_t skbase = smem_u32p(smKf);
    const uint32_t svbase = smem_u32p(smVf);
    float* smP = (float*)(sm + APOFF + w * 8704);   // warp-private [32][68]

#define AKV_ISSUE(stg, j0) do {                                               \
        uint32_t dk = skbase + (uint32_t)(stg) * AKSTG;                       \
        uint32_t dv = svbase + (uint32_t)(stg) * AVSTG;                       \
        _Pragma("unroll")                                                     \
        for (int r = 0; r < 8; r++) {                                         \
            int f = tid + r * 256;                                            \
            int key = f >> 4, sg = (f & 15);                                  \
            cp16(dk + (uint32_t)(key * 272 + sg * 16),                        \
                 g_k + base + (size_t)((j0) + key) * 1024 + sg * 4);          \
            cp16(dv + (uint32_t)(key * 288 + sg * 16),                        \
                 g_v + base + (size_t)((j0) + key) * 1024 + sg * 4);          \
        }                                                                     \
    } while (0)

    // ---- Q frags (tf32, pre-scaled by 1/8) ----
    uint32_t qf[8][2][4];
#pragma unroll
    for (int s = 0; s < 8; s++)
#pragma unroll
        for (int mf = 0; mf < 2; mf++) {
            const float* qp = g_q + base + (size_t)(rowbase + mf * 16 + lq) * 1024;
            int col = s * 8 + lr;
            qf[s][mf][0] = cvt_tf32(qp[col] * 0.125f);
            qf[s][mf][1] = cvt_tf32(qp[8 * 1024 + col] * 0.125f);
            qf[s][mf][2] = cvt_tf32(qp[col + 4] * 0.125f);
            qf[s][mf][3] = cvt_tf32(qp[8 * 1024 + col + 4] * 0.125f);
        }

    AKV_ISSUE(0, 0); CP_COMMIT();

    float o[2][8][4];
#pragma unroll
    for (int i = 0; i < 2; i++)
#pragma unroll
        for (int j = 0; j < 8; j++)
#pragma unroll
            for (int e = 0; e < 4; e++) o[i][j][e] = 0.0f;
    float rsa[2][2] = {{0.0f, 0.0f}, {0.0f, 0.0f}};

    for (int t = 0; t < 16; t++) {
        const int j0 = t * 128;
        const int st = t & 1;

        CP_WAIT0();
        __syncthreads();   // K/V(t) visible; stage st reads from t-2 done

        if (t < 15) AKV_ISSUE(st ^ 1, j0 + 128);
        CP_COMMIT();

        // ---- S = Q K^T (tf32) ----
        const float* sK = smKf + st * (AKSTG / 4);
        float sc[2][8][4];
#pragma unroll
        for (int i = 0; i < 2; i++)
#pragma unroll
            for (int j = 0; j < 8; j++)
#pragma unroll
                for (int e = 0; e < 4; e++) sc[i][j][e] = 0.0f;
#pragma unroll
        for (int s = 0; s < 8; s++) {
#pragma unroll
            for (int jf = 0; jf < 8; jf++) {
                const float* p = &sK[(kh * 64 + jf * 8 + lq) * 68 + s * 8 + lr];
                uint32_t b0 = cvt_tf32(p[0]);
                uint32_t b1 = cvt_tf32(p[4]);
                mma_tf32(sc[0][jf], qf[s][0], b0, b1);
                mma_tf32(sc[1][jf], qf[s][1], b0, b1);
            }
        }

        // ---- exp (max-free) + partial row sums + P -> warp smem ----
#pragma unroll
        for (int mf = 0; mf < 2; mf++)
#pragma unroll
            for (int jf = 0; jf < 8; jf++) {
                float e0 = __expf(sc[mf][jf][0]);
                float e1 = __expf(sc[mf][jf][1]);
                float e2 = __expf(sc[mf][jf][2]);
                float e3 = __expf(sc[mf][jf][3]);
                rsa[mf][0] += e0 + e1;
                rsa[mf][1] += e2 + e3;
                *(float2*)&smP[(mf * 16 + lq) * 68 + jf * 8 + lr * 2] =
                    make_float2(e0, e1);
                *(float2*)&smP[(mf * 16 + lq + 8) * 68 + jf * 8 + lr * 2] =
                    make_float2(e2, e3);
            }
        __syncwarp();

        // ---- O += P @ V (single-pass tf32, A from warp smem) ----
        const float* sV = smVf + st * (AVSTG / 4);
#pragma unroll
        for (int ks = 0; ks < 8; ks++) {
            uint32_t pa[2][4];
#pragma unroll
            for (int mf = 0; mf < 2; mf++) {
                const float* pp = &smP[(mf * 16 + lq) * 68 + ks * 8 + lr];
                pa[mf][0] = cvt_tf32(pp[0]);
                pa[mf][1] = cvt_tf32(pp[8 * 68]);
                pa[mf][2] = cvt_tf32(pp[4]);
                pa[mf][3] = cvt_tf32(pp[8 * 68 + 4]);
            }
            const float* vrow = &sV[(kh * 64 + ks * 8 + lr) * 72 + lq];
#pragma unroll
            for (int jd = 0; jd < 8; jd++) {
                uint32_t b0 = cvt_tf32(vrow[jd * 8]);
                uint32_t b1 = cvt_tf32(vrow[4 * 72 + jd * 8]);
                mma_tf32(o[0][jd], pa[0], b0, b1);
                mma_tf32(o[1][jd], pa[1], b0, b1);
            }
        }
    }

    // ---- merge key-half pairs, normalize, store ----
#pragma unroll
    for (int i = 0; i < 2; i++)
#pragma unroll
        for (int hh = 0; hh < 2; hh++) {
            rsa[i][hh] += __shfl_xor_sync(0xffffffffu, rsa[i][hh], 1);
            rsa[i][hh] += __shfl_xor_sync(0xffffffffu, rsa[i][hh], 2);
        }
    __syncthreads();
    if (kh == 1) {
#pragma unroll
        for (int mf = 0; mf < 2; mf++)
#pragma unroll
            for (int jf = 0; jf < 8; jf++)
#pragma unroll
                for (int e = 0; e < 4; e++) {
                    int idx = (mf * 8 + jf) * 4 + e;
                    smM[idx * 128 + qg * 32 + l] = o[mf][jf][e];
                }
#pragma unroll
        for (int i = 0; i < 4; i++)
            smM[8192 + i * 128 + qg * 32 + l] = rsa[i >> 1][i & 1];
    }
    __syncthreads();
    if (kh == 0) {
        float inv[2][2];
#pragma unroll
        for (int i = 0; i < 4; i++) {
            float tot = rsa[i >> 1][i & 1] + smM[8192 + i * 128 + qg * 32 + l];
            inv[i >> 1][i & 1] = 1.0f / tot;
        }
#pragma unroll
        for (int mf = 0; mf < 2; mf++)
#pragma unroll
            for (int jf = 0; jf < 8; jf++) {
                int idx = (mf * 8 + jf) * 4;
                float r0 = o[mf][jf][0] + smM[(idx + 0) * 128 + qg * 32 + l];
                float r1 = o[mf][jf][1] + smM[(idx + 1) * 128 + qg * 32 + l];
                float r2 = o[mf][jf][2] + smM[(idx + 2) * 128 + qg * 32 + l];
                float r3 = o[mf][jf][3] + smM[(idx + 3) * 128 + qg * 32 + l];
                int row = rowbase + mf * 16 + lq;
                int col = jf * 8 + lr * 2;
                *(float2*)(g_att + base + (size_t)row * 1024 + col) =
                    make_float2(r0 * inv[mf][0], r1 * inv[mf][0]);
                *(float2*)(g_att + base + (size_t)(row + 8) * 1024 + col) =
                    make_float2(r2 * inv[mf][1], r3 * inv[mf][1]);
            }
    }
#undef AKV_ISSUE
}

// =================== launch ===================
extern "C" void kernel_launch(void* const* d_in, const int* in_sizes, int n_in,
                              void* d_out, int out_size) {
    const float* hidden = (const float*)d_in[0];
    const float* wq     = (const float*)d_in[1];
    const float* wk     = (const float*)d_in[2];
    const float* wv     = (const float*)d_in[3];
    const float* wo     = (const float*)d_in[4];
    float* out = (float*)d_out;

    cudaFuncSetAttribute(qkv_mma, cudaFuncAttributeMaxDynamicSharedMemorySize, GEMM_SMEM);
    cudaFuncSetAttribute(out_mma, cudaFuncAttributeMaxDynamicSharedMemorySize, GEMM_SMEM);
    cudaFuncSetAttribute(attn_mma, cudaFuncAttributeMaxDynamicSharedMemorySize, ATT_SMEM);

    dim3 qkv_grid(8, 64, 3);
    qkv_mma<<<qkv_grid, 256, GEMM_SMEM>>>(hidden, wq, wk, wv);

    dim3 fa_grid(SEQ / 128, (MTOT / SEQ) * HEADS);  // (16, 64)
    attn_mma<<<fa_grid, 256, ATT_SMEM>>>();

    dim3 out_grid(8, 64);
    out_mma<<<out_grid, 256, GEMM_SMEM>>>(wo, out);

    (void)in_sizes; (void)n_in; (void)out_size;
}

// round 17
// speedup vs baseline: 1.4247x; 1.0686x over previous
#include <cuda_runtime.h>
#include <cuda_bf16.h>
#include <cstdint>

#define MTOT 8192
#define SEQ  2048
#define HEADS 16
#define NDIM 1024

__device__ float g_q[MTOT * NDIM];
__device__ float g_k[MTOT * NDIM];
__device__ float g_v[MTOT * NDIM];
__device__ float g_att[MTOT * NDIM];
// pre-rounded inputs
__device__ float g_h[MTOT * NDIM];
__device__ float g_wq[NDIM * NDIM];
__device__ float g_wk[NDIM * NDIM];
__device__ float g_wv[NDIM * NDIM];
__device__ float g_wo[NDIM * NDIM];

// ---- helpers ----
__device__ __forceinline__ uint32_t cvt_tf32(float x) {
    uint32_t u; asm("cvt.rna.tf32.f32 %0, %1;" : "=r"(u) : "f"(x));
    return u;
}
__device__ __forceinline__ float tf32f(float x) {
    return __uint_as_float(cvt_tf32(x));
}
__device__ __forceinline__ void mma_tf32(float* c, const uint32_t* a, uint32_t b0, uint32_t b1) {
    asm volatile(
        "mma.sync.aligned.m16n8k8.row.col.f32.tf32.tf32.f32 "
        "{%0,%1,%2,%3}, {%4,%5,%6,%7}, {%8,%9}, {%0,%1,%2,%3};"
        : "+f"(c[0]), "+f"(c[1]), "+f"(c[2]), "+f"(c[3])
        : "r"(a[0]), "r"(a[1]), "r"(a[2]), "r"(a[3]), "r"(b0), "r"(b1));
}
__device__ __forceinline__ uint32_t smem_u32p(const void* p) {
    return (uint32_t)__cvta_generic_to_shared(p);
}
__device__ __forceinline__ void cp16(uint32_t dst, const void* src) {
    asm volatile("cp.async.cg.shared.global [%0], [%1], 16;" :: "r"(dst), "l"(src));
}
#define CP_COMMIT() asm volatile("cp.async.commit_group;" ::: "memory")
#define CP_WAIT3()  asm volatile("cp.async.wait_group 3;" ::: "memory")
#define CP_WAIT0()  asm volatile("cp.async.wait_group 0;" ::: "memory")

// =================== pre-pass: RNA-round inputs into scratch ===================
__global__ void prep_round(const float* __restrict__ h, const float* __restrict__ wq,
                           const float* __restrict__ wk, const float* __restrict__ wv,
                           const float* __restrict__ wo) {
    const int H4 = (MTOT * NDIM) / 4;   // 2097152
    const int W4 = (NDIM * NDIM) / 4;   // 262144
    const int TOT = H4 + 4 * W4;
    for (int i = blockIdx.x * blockDim.x + threadIdx.x; i < TOT;
         i += gridDim.x * blockDim.x) {
        const float4* src; float4* dst; int j;
        if (i < H4)               { src = (const float4*)h;  dst = (float4*)g_h;  j = i; }
        else if (i < H4 + W4)     { src = (const float4*)wq; dst = (float4*)g_wq; j = i - H4; }
        else if (i < H4 + 2 * W4) { src = (const float4*)wk; dst = (float4*)g_wk; j = i - H4 - W4; }
        else if (i < H4 + 3 * W4) { src = (const float4*)wv; dst = (float4*)g_wv; j = i - H4 - 2 * W4; }
        else                      { src = (const float4*)wo; dst = (float4*)g_wo; j = i - H4 - 3 * W4; }
        float4 v = src[j];
        dst[j] = make_float4(tf32f(v.x), tf32f(v.y), tf32f(v.z), tf32f(v.w));
    }
}

// =================== GEMM (R14 shape; inputs pre-rounded, zero cvt) ===================
#define NSTG 5
#define STG_U32 4736
#define SB_OFF 2560
#define GEMM_SMEM (NSTG * STG_U32 * 4)

template <bool ROUND_OUT>
__device__ __forceinline__ void gemm_body(const float* __restrict__ A,
                                          const float* __restrict__ W,
                                          float* __restrict__ C) {
    extern __shared__ uint32_t smw[];
    const uint32_t sbase = smem_u32p(smw);

    const int tid = threadIdx.x, w = tid >> 5, l = tid & 31;
    const int lq = l >> 2, lr = l & 3;
    const int m0 = (w >> 2) * 64, n0 = (w & 3) * 32;
    const int bm = blockIdx.y * 128, bn = blockIdx.x * 128;

    const int arow_i = tid >> 1, ahalf = (tid & 1) * 8;
    const int kr = tid >> 4, nc = (tid & 15) * 8;

    const float* arow = A + (size_t)(bm + arow_i) * 1024 + ahalf;
    const float* brow = W + (size_t)kr * 1024 + bn + nc;
    const uint32_t dA0 = sbase + (uint32_t)(arow_i * 20 + ahalf) * 4;
    const uint32_t dB0 = sbase + (uint32_t)(SB_OFF + kr * 136 + nc) * 4;

#define G_ISSUE(p, c) do {                                                    \
        uint32_t dA = dA0 + (uint32_t)(p) * (STG_U32 * 4);                    \
        const float* ap = arow + (c) * 16;                                    \
        cp16(dA, ap); cp16(dA + 16, ap + 4);                                  \
        uint32_t dB = dB0 + (uint32_t)(p) * (STG_U32 * 4);                    \
        const float* bp = brow + (size_t)(c) * 16 * 1024;                     \
        cp16(dB, bp); cp16(dB + 16, bp + 4);                                  \
    } while (0)

    float acc[4][4][4];
#pragma unroll
    for (int i = 0; i < 4; i++)
#pragma unroll
        for (int j = 0; j < 4; j++)
#pragma unroll
            for (int e = 0; e < 4; e++) acc[i][j][e] = 0.0f;

    G_ISSUE(0, 0); CP_COMMIT();
    G_ISSUE(1, 1); CP_COMMIT();
    G_ISSUE(2, 2); CP_COMMIT();
    G_ISSUE(3, 3); CP_COMMIT();

    int st = 0, ist = 4;
    for (int c = 0; c < 64; c++) {
        CP_WAIT3();
        __syncthreads();

        if (c + 4 < 64) G_ISSUE(ist, c + 4);
        CP_COMMIT();

        const uint32_t* sA = smw + st * STG_U32;
        const uint32_t* sB = sA + SB_OFF;
#pragma unroll
        for (int s = 0; s < 2; s++) {
            uint32_t a[4][4];
#pragma unroll
            for (int mf = 0; mf < 4; mf++) {
                const uint32_t* p = &sA[(m0 + mf * 16 + lq) * 20 + s * 8 + lr];
                a[mf][0] = p[0];
                a[mf][1] = p[8 * 20];
                a[mf][2] = p[4];
                a[mf][3] = p[8 * 20 + 4];
            }
            const uint32_t* q0p = &sB[(s * 8 + lr) * 136 + n0 + lq];
            const uint32_t* q1p = q0p + 4 * 136;
#pragma unroll
            for (int jf = 0; jf < 4; jf++) {
                uint32_t b0 = q0p[jf * 8];
                uint32_t b1 = q1p[jf * 8];
                mma_tf32(acc[0][jf], a[0], b0, b1);
                mma_tf32(acc[1][jf], a[1], b0, b1);
                mma_tf32(acc[2][jf], a[2], b0, b1);
                mma_tf32(acc[3][jf], a[3], b0, b1);
            }
        }
        st = (st == NSTG - 1) ? 0 : st + 1;
        ist = (ist == NSTG - 1) ? 0 : ist + 1;
    }

#pragma unroll
    for (int mf = 0; mf < 4; mf++)
#pragma unroll
        for (int jf = 0; jf < 4; jf++) {
            int row = bm + m0 + mf * 16 + lq;
            int col = bn + n0 + jf * 8 + lr * 2;
            if (ROUND_OUT) {
                *(float2*)(C + (size_t)row * 1024 + col) =
                    make_float2(tf32f(acc[mf][jf][0]), tf32f(acc[mf][jf][1]));
                *(float2*)(C + (size_t)(row + 8) * 1024 + col) =
                    make_float2(tf32f(acc[mf][jf][2]), tf32f(acc[mf][jf][3]));
            } else {
                *(float2*)(C + (size_t)row * 1024 + col) =
                    make_float2(acc[mf][jf][0], acc[mf][jf][1]);
                *(float2*)(C + (size_t)(row + 8) * 1024 + col) =
                    make_float2(acc[mf][jf][2], acc[mf][jf][3]);
            }
        }
#undef G_ISSUE
}

__global__ void __launch_bounds__(256, 2)
qkv_mma() {
    const float* W = (blockIdx.z == 0) ? g_wq : (blockIdx.z == 1) ? g_wk : g_wv;
    float* C       = (blockIdx.z == 0) ? g_q : (blockIdx.z == 1) ? g_k : g_v;
    gemm_body<true>(g_h, W, C);
}
__global__ void __launch_bounds__(256, 2)
out_mma(float* __restrict__ out) {
    gemm_body<false>(g_att, g_wo, out);
}

// =================== Attention (pre-rounded K/V/Q; tf32 PV via warp smem P) ===================
#define AKSTG 34816
#define AVSTG 36864
#define APOFF (2 * AKSTG + 2 * AVSTG)
#define ATT_SMEM (APOFF + 8 * 8704)

__global__ void attn_mma() {
    extern __shared__ char sm[];
    float* smKf = (float*)sm;
    float* smVf = (float*)(sm + 2 * AKSTG);
    float* smM = (float*)sm;

    const int tid = threadIdx.x, w = tid >> 5, l = tid & 31;
    const int lq = l >> 2, lr = l & 3;
    const int qg = w >> 1, kh = w & 1;
    const int b = blockIdx.y >> 4, h = blockIdx.y & 15;
    const size_t base = (size_t)b * SEQ * NDIM + (size_t)h * 64;
    const int q0 = blockIdx.x * 128;
    const int rowbase = q0 + qg * 32;
    const uint32_t skbase = smem_u32p(smKf);
    const uint32_t svbase = smem_u32p(smVf);
    float* smP = (float*)(sm + APOFF + w * 8704);

#define AKV_ISSUE(stg, j0) do {                                               \
        uint32_t dk = skbase + (uint32_t)(stg) * AKSTG;                       \
        uint32_t dv = svbase + (uint32_t)(stg) * AVSTG;                       \
        _Pragma("unroll")                                                     \
        for (int r = 0; r < 8; r++) {                                         \
            int f = tid + r * 256;                                            \
            int key = f >> 4, sg = (f & 15);                                  \
            cp16(dk + (uint32_t)(key * 272 + sg * 16),                        \
                 g_k + base + (size_t)((j0) + key) * 1024 + sg * 4);          \
            cp16(dv + (uint32_t)(key * 288 + sg * 16),                        \
                 g_v + base + (size_t)((j0) + key) * 1024 + sg * 4);          \
        }                                                                     \
    } while (0)

    // Q frags: g_q pre-rounded; x0.125 (power of 2) keeps tf32 exact — no cvt
    uint32_t qf[8][2][4];
#pragma unroll
    for (int s = 0; s < 8; s++)
#pragma unroll
        for (int mf = 0; mf < 2; mf++) {
            const float* qp = g_q + base + (size_t)(rowbase + mf * 16 + lq) * 1024;
            int col = s * 8 + lr;
            qf[s][mf][0] = __float_as_uint(qp[col] * 0.125f);
            qf[s][mf][1] = __float_as_uint(qp[8 * 1024 + col] * 0.125f);
            qf[s][mf][2] = __float_as_uint(qp[col + 4] * 0.125f);
            qf[s][mf][3] = __float_as_uint(qp[8 * 1024 + col + 4] * 0.125f);
        }

    AKV_ISSUE(0, 0); CP_COMMIT();

    float o[2][8][4];
#pragma unroll
    for (int i = 0; i < 2; i++)
#pragma unroll
        for (int j = 0; j < 8; j++)
#pragma unroll
            for (int e = 0; e < 4; e++) o[i][j][e] = 0.0f;
    float rsa[2][2] = {{0.0f, 0.0f}, {0.0f, 0.0f}};

    for (int t = 0; t < 16; t++) {
        const int j0 = t * 128;
        const int st = t & 1;

        CP_WAIT0();
        __syncthreads();

        if (t < 15) AKV_ISSUE(st ^ 1, j0 + 128);
        CP_COMMIT();

        // ---- S = Q K^T (tf32), K pre-rounded -> direct bit loads ----
        const uint32_t* sK = (const uint32_t*)(smKf + st * (AKSTG / 4));
        float sc[2][8][4];
#pragma unroll
        for (int i = 0; i < 2; i++)
#pragma unroll
            for (int j = 0; j < 8; j++)
#pragma unroll
                for (int e = 0; e < 4; e++) sc[i][j][e] = 0.0f;
#pragma unroll
        for (int s = 0; s < 8; s++) {
#pragma unroll
            for (int jf = 0; jf < 8; jf++) {
                const uint32_t* p = &sK[(kh * 64 + jf * 8 + lq) * 68 + s * 8 + lr];
                uint32_t b0 = p[0];
                uint32_t b1 = p[4];
                mma_tf32(sc[0][jf], qf[s][0], b0, b1);
                mma_tf32(sc[1][jf], qf[s][1], b0, b1);
            }
        }

        // ---- exp + row sums + P (tf32-rounded at STS) ----
#pragma unroll
        for (int mf = 0; mf < 2; mf++)
#pragma unroll
            for (int jf = 0; jf < 8; jf++) {
                float e0 = __expf(sc[mf][jf][0]);
                float e1 = __expf(sc[mf][jf][1]);
                float e2 = __expf(sc[mf][jf][2]);
                float e3 = __expf(sc[mf][jf][3]);
                rsa[mf][0] += e0 + e1;
                rsa[mf][1] += e2 + e3;
                *(float2*)&smP[(mf * 16 + lq) * 68 + jf * 8 + lr * 2] =
                    make_float2(tf32f(e0), tf32f(e1));
                *(float2*)&smP[(mf * 16 + lq + 8) * 68 + jf * 8 + lr * 2] =
                    make_float2(tf32f(e2), tf32f(e3));
            }
        __syncwarp();

        // ---- O += P @ V (tf32, V pre-rounded) ----
        const uint32_t* sV = (const uint32_t*)(smVf + st * (AVSTG / 4));
#pragma unroll
        for (int ks = 0; ks < 8; ks++) {
            uint32_t pa[2][4];
#pragma unroll
            for (int mf = 0; mf < 2; mf++) {
                const uint32_t* pp = (const uint32_t*)&smP[(mf * 16 + lq) * 68 + ks * 8 + lr];
                pa[mf][0] = pp[0];
                pa[mf][1] = pp[8 * 68];
                pa[mf][2] = pp[4];
                pa[mf][3] = pp[8 * 68 + 4];
            }
            const uint32_t* vrow = &sV[(kh * 64 + ks * 8 + lr) * 72 + lq];
#pragma unroll
            for (int jd = 0; jd < 8; jd++) {
                uint32_t b0 = vrow[jd * 8];
                uint32_t b1 = vrow[4 * 72 + jd * 8];
                mma_tf32(o[0][jd], pa[0], b0, b1);
                mma_tf32(o[1][jd], pa[1], b0, b1);
            }
        }
    }

    // ---- merge, normalize, store (rounded for out_mma) ----
#pragma unroll
    for (int i = 0; i < 2; i++)
#pragma unroll
        for (int hh = 0; hh < 2; hh++) {
            rsa[i][hh] += __shfl_xor_sync(0xffffffffu, rsa[i][hh], 1);
            rsa[i][hh] += __shfl_xor_sync(0xffffffffu, rsa[i][hh], 2);
        }
    __syncthreads();
    if (kh == 1) {
#pragma unroll
        for (int mf = 0; mf < 2; mf++)
#pragma unroll
            for (int jf = 0; jf < 8; jf++)
#pragma unroll
                for (int e = 0; e < 4; e++) {
                    int idx = (mf * 8 + jf) * 4 + e;
                    smM[idx * 128 + qg * 32 + l] = o[mf][jf][e];
                }
#pragma unroll
        for (int i = 0; i < 4; i++)
            smM[8192 + i * 128 + qg * 32 + l] = rsa[i >> 1][i & 1];
    }
    __syncthreads();
    if (kh == 0) {
        float inv[2][2];
#pragma unroll
        for (int i = 0; i < 4; i++) {
            float tot = rsa[i >> 1][i & 1] + smM[8192 + i * 128 + qg * 32 + l];
            inv[i >> 1][i & 1] = 1.0f / tot;
        }
#pragma unroll
        for (int mf = 0; mf < 2; mf++)
#pragma unroll
            for (int jf = 0; jf < 8; jf++) {
                int idx = (mf * 8 + jf) * 4;
                float r0 = o[mf][jf][0] + smM[(idx + 0) * 128 + qg * 32 + l];
                float r1 = o[mf][jf][1] + smM[(idx + 1) * 128 + qg * 32 + l];
                float r2 = o[mf][jf][2] + smM[(idx + 2) * 128 + qg * 32 + l];
                float r3 = o[mf][jf][3] + smM[(idx + 3) * 128 + qg * 32 + l];
                int row = rowbase + mf * 16 + lq;
                int col = jf * 8 + lr * 2;
                *(float2*)(g_att + base + (size_t)row * 1024 + col) =
                    make_float2(tf32f(r0 * inv[mf][0]), tf32f(r1 * inv[mf][0]));
                *(float2*)(g_att + base + (size_t)(row + 8) * 1024 + col) =
                    make_float2(tf32f(r2 * inv[mf][1]), tf32f(r3 * inv[mf][1]));
            }
    }
#undef AKV_ISSUE
}

// =================== launch ===================
extern "C" void kernel_launch(void* const* d_in, const int* in_sizes, int n_in,
                              void* d_out, int out_size) {
    const float* hidden = (const float*)d_in[0];
    const float* wq     = (const float*)d_in[1];
    const float* wk     = (const float*)d_in[2];
    const float* wv     = (const float*)d_in[3];
    const float* wo     = (const float*)d_in[4];
    float* out = (float*)d_out;

    cudaFuncSetAttribute(qkv_mma, cudaFuncAttributeMaxDynamicSharedMemorySize, GEMM_SMEM);
    cudaFuncSetAttribute(out_mma, cudaFuncAttributeMaxDynamicSharedMemorySize, GEMM_SMEM);
    cudaFuncSetAttribute(attn_mma, cudaFuncAttributeMaxDynamicSharedMemorySize, ATT_SMEM);

    prep_round<<<1184, 256>>>(hidden, wq, wk, wv, wo);

    dim3 qkv_grid(8, 64, 3);
    qkv_mma<<<qkv_grid, 256, GEMM_SMEM>>>();

    dim3 fa_grid(SEQ / 128, (MTOT / SEQ) * HEADS);  // (16, 64)
    attn_mma<<<fa_grid, 256, ATT_SMEM>>>();

    dim3 out_grid(8, 64);
    out_mma<<<out_grid, 256, GEMM_SMEM>>>(out);

    (void)in_sizes; (void)n_in; (void)out_size;
}